// round 9
// baseline (speedup 1.0000x reference)
#include <cuda_runtime.h>
#include <cuda_bf16.h>

// emdModule: exact NN via uniform-grid spatial hashing + 50-step recurrence.
//
// EXACTNESS ARGUMENT (outputs bit-identical to the passing brute-force):
//  - d2 for every examined candidate uses the identical rounded op sequence:
//      w     = (a*a + b*b) + c*c                       (mul/add, no fma)
//      inner = fma(z,c, fma(y,b, x*a))
//      d2    = fma(-2, inner, sq1 + w)
//  - selection = min over packed key (bits(d2)<<32 | j): order-independent,
//    ties broken toward smaller j == jnp.argmin first-index. Scatter order of
//    the counting sort therefore cannot affect the result.
//  - completeness: after scanning the Chebyshev<=r cell cube around the query,
//    any unexamined point has exact distance >= r*h (query lies inside its own
//    cell), so its rounded d2 >= (r*h)^2 - 2e-6. We stop only when
//    best_d2 < (r*h)^2 - 1e-5, so the global min key is already examined.
//    Fallback: full-grid coverage always terminates the loop.
//  - epilogue identical: cmin = sqrt(max(d2,0)); 50x {m = cmin - price;
//    price += eps*m}; outputs sqrt(m), assignment.

#define BATCH 16
#define NPTS 2048
#define ROWS (BATCH * NPTS)   // 32768
#define G 16                  // grid resolution per axis
#define CELLS (G * G * G)     // 4096
#define HCELL 0.0625f         // 1/G, exactly representable

// Scratch (static __device__ per allocation rules):
//   g_pts[b][slot] = {a, b, c, j-as-bits}, cell-sorted per batch
//   g_cs [b][cell] = exclusive start; g_cs[b][4096] = NPTS sentinel
__device__ float4 g_pts[BATCH * NPTS];
__device__ int    g_cs[BATCH * (CELLS + 1)];

__device__ __forceinline__ int cell_coord(float v) {
    int c = (int)(v * (float)G);
    return c < 0 ? 0 : (c > G - 1 ? G - 1 : c);
}

// ---------------- Kernel A: per-batch counting sort into cells -------------
#define TPB_A 512
#define PPT_A (NPTS / TPB_A)      // 4 points per thread
#define CPT_A (CELLS / TPB_A)     // 8 cells per thread

__global__ void __launch_bounds__(TPB_A) emd_bin_kernel(
    const float* __restrict__ x2) {
    int b = blockIdx.x;
    int t = threadIdx.x;
    __shared__ int cnt[CELLS];
    __shared__ int wsum[16];

    for (int c = t; c < CELLS; c += TPB_A) cnt[c] = 0;
    __syncthreads();

    // Count (cache cell ids + coords for the scatter pass)
    int   cellof[PPT_A];
    float px[PPT_A], py[PPT_A], pz[PPT_A];
    #pragma unroll
    for (int s = 0; s < PPT_A; s++) {
        int k = t + s * TPB_A;
        const float* p = x2 + ((long)b * NPTS + k) * 3;
        float a = p[0], bb = p[1], cc = p[2];
        int c = (cell_coord(cc) * G + cell_coord(bb)) * G + cell_coord(a);
        px[s] = a; py[s] = bb; pz[s] = cc; cellof[s] = c;
        atomicAdd(&cnt[c], 1);
    }
    __syncthreads();

    // Block-wide exclusive prefix sum over 4096 cells (8 per thread)
    int loc[CPT_A], tsum = 0;
    #pragma unroll
    for (int u = 0; u < CPT_A; u++) { loc[u] = cnt[t * CPT_A + u]; tsum += loc[u]; }
    int lane = t & 31, wid = t >> 5;
    int incl = tsum;
    #pragma unroll
    for (int off = 1; off < 32; off <<= 1) {
        int v = __shfl_up_sync(0xFFFFFFFFu, incl, off);
        if (lane >= off) incl += v;
    }
    if (lane == 31) wsum[wid] = incl;
    __syncthreads();
    if (t == 0) {
        int acc = 0;
        #pragma unroll
        for (int w = 0; w < 16; w++) { int v = wsum[w]; wsum[w] = acc; acc += v; }
    }
    __syncthreads();
    int run = wsum[wid] + (incl - tsum);   // exclusive base for this thread
    __syncthreads();                        // all reads of cnt done before reuse
    #pragma unroll
    for (int u = 0; u < CPT_A; u++) {
        int c = t * CPT_A + u;
        g_cs[b * (CELLS + 1) + c] = run;
        cnt[c] = run;                       // reuse as scatter cursor
        run += loc[u];
    }
    if (t == 0) g_cs[b * (CELLS + 1) + CELLS] = NPTS;
    __syncthreads();

    // Scatter (slot order within a cell is arbitrary; selection is a key-min
    // so the result is order-independent)
    #pragma unroll
    for (int s = 0; s < PPT_A; s++) {
        int k = t + s * TPB_A;
        int slot = atomicAdd(&cnt[cellof[s]], 1);
        g_pts[b * NPTS + slot] =
            make_float4(px[s], py[s], pz[s], __int_as_float(k));
    }
}

// ---------------- Kernel B: grid NN query + epilogue -----------------------
typedef unsigned long long u64;

__global__ void __launch_bounds__(128) emd_query_kernel(
    const float* __restrict__ x1, float* __restrict__ out,
    const float* __restrict__ eps_p, const int* __restrict__ iters_p,
    int write_assign) {
    int gid = blockIdx.x * blockDim.x + threadIdx.x;
    if (gid >= ROWS) return;
    int b = gid >> 11;            // / NPTS
    int i = gid & (NPTS - 1);

    const float* pq = x1 + ((long)b * NPTS + i) * 3;
    float x = pq[0], y = pq[1], z = pq[2];
    float sq1 = __fadd_rn(__fadd_rn(__fmul_rn(x, x), __fmul_rn(y, y)),
                          __fmul_rn(z, z));
    int cx = cell_coord(x), cy = cell_coord(y), cz = cell_coord(z);

    const float4* pts = g_pts + b * NPTS;
    const int*    cs  = g_cs + b * (CELLS + 1);

    u64 best = 0xFFFFFFFFFFFFFFFFull;
    for (int r = 1; r <= G; r++) {
        int z0 = cz - r < 0 ? 0 : cz - r, z1 = cz + r > G - 1 ? G - 1 : cz + r;
        int y0 = cy - r < 0 ? 0 : cy - r, y1 = cy + r > G - 1 ? G - 1 : cy + r;
        int x0 = cx - r < 0 ? 0 : cx - r, x1 = cx + r > G - 1 ? G - 1 : cx + r;
        for (int zc = z0; zc <= z1; zc++) {
            for (int yc = y0; yc <= y1; yc++) {
                int row = (zc * G + yc) * G;
                int s = cs[row + x0];
                int e = cs[row + x1 + 1];   // contiguous x-run of cells
                for (int k = s; k < e; k++) {
                    float4 p = pts[k];
                    float w = __fadd_rn(
                        __fadd_rn(__fmul_rn(p.x, p.x), __fmul_rn(p.y, p.y)),
                        __fmul_rn(p.z, p.z));
                    float inner = __fmaf_rn(z, p.z,
                                  __fmaf_rn(y, p.y, __fmul_rn(x, p.x)));
                    float d2 = __fmaf_rn(-2.0f, inner, __fadd_rn(sq1, w));
                    u64 key = ((u64)__float_as_uint(d2) << 32) |
                              (unsigned)__float_as_int(p.w);
                    if (key < best) best = key;
                }
            }
        }
        // Unexamined points have exact dist >= r*h => rounded d2 >= (rh)^2-2e-6
        float rh = (float)r * HCELL;
        float bd2 = __uint_as_float((unsigned)(best >> 32));
        if (bd2 < rh * rh - 1e-5f) break;
        if (x0 == 0 && x1 == G - 1 && y0 == 0 && y1 == G - 1 &&
            z0 == 0 && z1 == G - 1) break;          // full grid scanned
    }

    float d2 = __uint_as_float((unsigned)(best >> 32));
    int   aj = (int)(best & 0xFFFFFFFFu);

    float cmin = sqrtf(fmaxf(d2, 0.0f));            // IEEE sqrt
    float eps  = eps_p   ? *eps_p   : 0.005f;
    int   iters = iters_p ? *iters_p : 50;

    float price = 0.0f;
    float m = 0.0f;
    for (int t = 0; t < iters; t++) {
        m = __fadd_rn(cmin, -price);                 // c_min - price
        price = __fadd_rn(price, __fmul_rn(eps, m)); // price += eps*m
    }

    out[gid] = sqrtf(m);
    if (write_assign) out[ROWS + gid] = (float)aj;
}

extern "C" void kernel_launch(void* const* d_in, const int* in_sizes, int n_in,
                              void* d_out, int out_size) {
    const float* x1 = (const float*)d_in[0];
    const float* x2 = (const float*)d_in[1];
    const float* eps_p   = (n_in > 2) ? (const float*)d_in[2] : nullptr;
    const int*   iters_p = (n_in > 3) ? (const int*)d_in[3]   : nullptr;

    emd_bin_kernel<<<BATCH, TPB_A>>>(x2);

    int write_assign = (out_size >= 2 * ROWS) ? 1 : 0;
    emd_query_kernel<<<ROWS / 128, 128>>>(x1, (float*)d_out,
                                          eps_p, iters_p, write_assign);
}

// round 10
// speedup vs baseline: 1.1967x; 1.1967x over previous
#include <cuda_runtime.h>
#include <cuda_bf16.h>

// emdModule: exact NN via uniform-grid spatial hashing + 50-step recurrence.
// Warp-per-query: lanes scan cell-cube rows in parallel, shfl-butterfly merge.
//
// EXACTNESS (outputs bit-identical to the passing brute-force kernels):
//  - d2 for every examined candidate uses the identical rounded op sequence:
//      w     = (a*a + b*b) + c*c                       (mul/add, no fma)
//      inner = fma(z,c, fma(y,b, x*a))
//      d2    = fma(-2, inner, sq1 + w)
//  - selection = min over packed key (bits(d2)<<32 | j): order- and
//    duplication-independent; ties -> smaller j == jnp.argmin first-index.
//    Lane partitioning / rescans therefore cannot change the result.
//  - completeness: after scanning the Chebyshev<=r cell cube, any unexamined
//    point differs by >= r+1 cells on some axis => exact distance >= r*h, so
//    rounded d2 >= (r*h)^2 - ~2e-6. We stop only when
//    best_d2 < (r*h)^2 - 1e-5; full-cube coverage is the fallback.
//  - epilogue identical: cmin = sqrt(max(d2,0)); 50x {m = cmin - price;
//    price += eps*m}; outputs sqrt(m), assignment.

#define BATCH 16
#define NPTS 2048
#define ROWS (BATCH * NPTS)   // 32768
#define G 16                  // grid resolution per axis
#define CELLS (G * G * G)     // 4096
#define HCELL 0.0625f         // 1/G, exactly representable

__device__ float4 g_pts[BATCH * NPTS];          // {a,b,c, j-as-bits} cell-sorted
__device__ int    g_cs[BATCH * (CELLS + 1)];    // exclusive starts + sentinel

__device__ __forceinline__ int cell_coord(float v) {
    int c = (int)(v * (float)G);
    return c < 0 ? 0 : (c > G - 1 ? G - 1 : c);
}

// ---------------- Kernel A: per-batch counting sort into cells -------------
#define TPB_A 512
#define PPT_A (NPTS / TPB_A)      // 4 points per thread
#define CPT_A (CELLS / TPB_A)     // 8 cells per thread

__global__ void __launch_bounds__(TPB_A) emd_bin_kernel(
    const float* __restrict__ x2) {
    int b = blockIdx.x;
    int t = threadIdx.x;
    __shared__ int cnt[CELLS];
    __shared__ int wsum[16];

    for (int c = t; c < CELLS; c += TPB_A) cnt[c] = 0;
    __syncthreads();

    int   cellof[PPT_A];
    float px[PPT_A], py[PPT_A], pz[PPT_A];
    #pragma unroll
    for (int s = 0; s < PPT_A; s++) {
        int k = t + s * TPB_A;
        const float* p = x2 + ((long)b * NPTS + k) * 3;
        float a = p[0], bb = p[1], cc = p[2];
        int c = (cell_coord(cc) * G + cell_coord(bb)) * G + cell_coord(a);
        px[s] = a; py[s] = bb; pz[s] = cc; cellof[s] = c;
        atomicAdd(&cnt[c], 1);
    }
    __syncthreads();

    // Block-wide exclusive prefix sum over 4096 cells (8 per thread)
    int loc[CPT_A], tsum = 0;
    #pragma unroll
    for (int u = 0; u < CPT_A; u++) { loc[u] = cnt[t * CPT_A + u]; tsum += loc[u]; }
    int lane = t & 31, wid = t >> 5;
    int incl = tsum;
    #pragma unroll
    for (int off = 1; off < 32; off <<= 1) {
        int v = __shfl_up_sync(0xFFFFFFFFu, incl, off);
        if (lane >= off) incl += v;
    }
    if (lane == 31) wsum[wid] = incl;
    __syncthreads();
    if (t == 0) {
        int acc = 0;
        #pragma unroll
        for (int w = 0; w < 16; w++) { int v = wsum[w]; wsum[w] = acc; acc += v; }
    }
    __syncthreads();
    int run = wsum[wid] + (incl - tsum);
    __syncthreads();                        // cnt reads done before reuse
    #pragma unroll
    for (int u = 0; u < CPT_A; u++) {
        int c = t * CPT_A + u;
        g_cs[b * (CELLS + 1) + c] = run;
        cnt[c] = run;                       // reuse as scatter cursor
        run += loc[u];
    }
    if (t == 0) g_cs[b * (CELLS + 1) + CELLS] = NPTS;
    __syncthreads();

    #pragma unroll
    for (int s = 0; s < PPT_A; s++) {
        int k = t + s * TPB_A;
        int slot = atomicAdd(&cnt[cellof[s]], 1);
        g_pts[b * NPTS + slot] =
            make_float4(px[s], py[s], pz[s], __int_as_float(k));
    }
}

// ---------------- Kernel B: warp-per-query grid NN + epilogue --------------
typedef unsigned long long u64;
#define TPB_B 256
#define QPB (TPB_B / 32)          // 8 queries (warps) per block

__global__ void __launch_bounds__(TPB_B) emd_query_kernel(
    const float* __restrict__ x1, float* __restrict__ out,
    const float* __restrict__ eps_p, const int* __restrict__ iters_p,
    int write_assign) {
    int warp = threadIdx.x >> 5;
    int lane = threadIdx.x & 31;
    int gid  = blockIdx.x * QPB + warp;      // query id
    int b = gid >> 11;                        // / NPTS
    // gid < ROWS always (grid sized exactly)

    const float* pq = x1 + (long)gid * 3;
    float x = pq[0], y = pq[1], z = pq[2];
    float sq1 = __fadd_rn(__fadd_rn(__fmul_rn(x, x), __fmul_rn(y, y)),
                          __fmul_rn(z, z));
    int cx = cell_coord(x), cy = cell_coord(y), cz = cell_coord(z);

    const float4* pts = g_pts + b * NPTS;
    const int*    cs  = g_cs + b * (CELLS + 1);

    u64 best = 0xFFFFFFFFFFFFFFFFull;        // lane-local, then warp-merged
    for (int r = 1; r <= G; r++) {
        int z0 = cz - r < 0 ? 0 : cz - r, z1 = cz + r > G - 1 ? G - 1 : cz + r;
        int y0 = cy - r < 0 ? 0 : cy - r, y1 = cy + r > G - 1 ? G - 1 : cy + r;
        int x0 = cx - r < 0 ? 0 : cx - r, x1 = cx + r > G - 1 ? G - 1 : cx + r;
        int ny   = y1 - y0 + 1;
        int nrow = (z1 - z0 + 1) * ny;

        // Lanes take (zc,yc) rows in parallel; each row's cells are an
        // x-contiguous run => one [s,e) candidate range per row.
        for (int t = lane; t < nrow; t += 32) {
            int zc = z0 + t / ny;
            int yc = y0 + (t - (t / ny) * ny);
            int row = (zc * G + yc) * G;
            int s = cs[row + x0];
            int e = cs[row + x1 + 1];
            for (int k = s; k < e; k++) {
                float4 p = pts[k];
                float w = __fadd_rn(
                    __fadd_rn(__fmul_rn(p.x, p.x), __fmul_rn(p.y, p.y)),
                    __fmul_rn(p.z, p.z));
                float inner = __fmaf_rn(z, p.z,
                              __fmaf_rn(y, p.y, __fmul_rn(x, p.x)));
                float d2 = __fmaf_rn(-2.0f, inner, __fadd_rn(sq1, w));
                u64 key = ((u64)__float_as_uint(d2) << 32) |
                          (unsigned)__float_as_int(p.w);
                if (key < best) best = key;
            }
        }

        // Warp butterfly u64-min: all lanes end with the warp best.
        #pragma unroll
        for (int off = 16; off > 0; off >>= 1) {
            u64 o = __shfl_xor_sync(0xFFFFFFFFu, best, off);
            if (o < best) best = o;
        }

        float rh  = (float)r * HCELL;
        float bd2 = __uint_as_float((unsigned)(best >> 32));
        if (bd2 < rh * rh - 1e-5f) break;    // provably complete
        if (x0 == 0 && x1 == G - 1 && y0 == 0 && y1 == G - 1 &&
            z0 == 0 && z1 == G - 1) break;   // full grid scanned
    }

    if (lane == 0) {
        float d2 = __uint_as_float((unsigned)(best >> 32));
        int   aj = (int)(best & 0xFFFFFFFFu);

        float cmin = sqrtf(fmaxf(d2, 0.0f));            // IEEE sqrt
        float eps  = eps_p   ? *eps_p   : 0.005f;
        int   iters = iters_p ? *iters_p : 50;

        float price = 0.0f;
        float m = 0.0f;
        for (int t = 0; t < iters; t++) {
            m = __fadd_rn(cmin, -price);                 // c_min - price
            price = __fadd_rn(price, __fmul_rn(eps, m)); // price += eps*m
        }

        out[gid] = sqrtf(m);
        if (write_assign) out[ROWS + gid] = (float)aj;
    }
}

extern "C" void kernel_launch(void* const* d_in, const int* in_sizes, int n_in,
                              void* d_out, int out_size) {
    const float* x1 = (const float*)d_in[0];
    const float* x2 = (const float*)d_in[1];
    const float* eps_p   = (n_in > 2) ? (const float*)d_in[2] : nullptr;
    const int*   iters_p = (n_in > 3) ? (const int*)d_in[3]   : nullptr;

    emd_bin_kernel<<<BATCH, TPB_A>>>(x2);

    int write_assign = (out_size >= 2 * ROWS) ? 1 : 0;
    emd_query_kernel<<<ROWS / QPB, TPB_B>>>(x1, (float*)d_out,
                                            eps_p, iters_p, write_assign);
}

// round 11
// speedup vs baseline: 1.3661x; 1.1415x over previous
#include <cuda_runtime.h>
#include <cuda_bf16.h>

// emdModule: exact NN via uniform-grid spatial hashing + 50-step recurrence.
// 8 lanes per query (4 queries/warp): amortizes warp overhead, keeps latency
// hidden. r=1 fast path (constant-divisor row mapping), rare general fallback.
//
// EXACTNESS (outputs bit-identical to the passing brute-force kernels):
//  - d2 per examined candidate uses the identical rounded op sequence:
//      w     = (a*a + b*b) + c*c                       (mul/add, no fma)
//      inner = fma(z,c, fma(y,b, x*a))
//      d2    = fma(-2, inner, sq1 + w)
//  - selection = min over packed key (bits(d2)<<32 | j): order- and
//    duplication-independent; ties -> smaller j == jnp.argmin first-index.
//  - completeness: after scanning the Chebyshev<=r cell cube, any unexamined
//    point is >= r cells away on some axis => exact dist >= r*h, so rounded
//    d2 >= (r*h)^2 - ~2e-6. Stop only when best_d2 < (r*h)^2 - 1e-5;
//    r reaching G covers the whole grid as fallback.
//  - epilogue identical: cmin = sqrt(max(d2,0)); iters x {m = cmin - price;
//    price += eps*m}; outputs sqrt(m), assignment.

#define BATCH 16
#define NPTS 2048
#define ROWS (BATCH * NPTS)   // 32768
#define G 16                  // grid resolution per axis
#define CELLS (G * G * G)     // 4096
#define HCELL 0.0625f         // 1/G, exactly representable

__device__ float4 g_pts[BATCH * NPTS];          // {a,b,c, j-as-bits} cell-sorted
__device__ int    g_cs[BATCH * (CELLS + 1)];    // exclusive starts + sentinel

__device__ __forceinline__ int cell_coord(float v) {
    int c = (int)(v * (float)G);
    return c < 0 ? 0 : (c > G - 1 ? G - 1 : c);
}

// ---------------- Kernel A: per-batch counting sort into cells -------------
#define TPB_A 512
#define PPT_A (NPTS / TPB_A)      // 4 points per thread
#define CPT_A (CELLS / TPB_A)     // 8 cells per thread

__global__ void __launch_bounds__(TPB_A) emd_bin_kernel(
    const float* __restrict__ x2) {
    int b = blockIdx.x;
    int t = threadIdx.x;
    __shared__ int cnt[CELLS];
    __shared__ int wsum[16];

    for (int c = t; c < CELLS; c += TPB_A) cnt[c] = 0;
    __syncthreads();

    int   cellof[PPT_A];
    float px[PPT_A], py[PPT_A], pz[PPT_A];
    #pragma unroll
    for (int s = 0; s < PPT_A; s++) {
        int k = t + s * TPB_A;
        const float* p = x2 + ((long)b * NPTS + k) * 3;
        float a = p[0], bb = p[1], cc = p[2];
        int c = (cell_coord(cc) * G + cell_coord(bb)) * G + cell_coord(a);
        px[s] = a; py[s] = bb; pz[s] = cc; cellof[s] = c;
        atomicAdd(&cnt[c], 1);
    }
    __syncthreads();

    int loc[CPT_A], tsum = 0;
    #pragma unroll
    for (int u = 0; u < CPT_A; u++) { loc[u] = cnt[t * CPT_A + u]; tsum += loc[u]; }
    int lane = t & 31, wid = t >> 5;
    int incl = tsum;
    #pragma unroll
    for (int off = 1; off < 32; off <<= 1) {
        int v = __shfl_up_sync(0xFFFFFFFFu, incl, off);
        if (lane >= off) incl += v;
    }
    if (lane == 31) wsum[wid] = incl;
    __syncthreads();
    if (t == 0) {
        int acc = 0;
        #pragma unroll
        for (int w = 0; w < 16; w++) { int v = wsum[w]; wsum[w] = acc; acc += v; }
    }
    __syncthreads();
    int run = wsum[wid] + (incl - tsum);
    __syncthreads();
    #pragma unroll
    for (int u = 0; u < CPT_A; u++) {
        int c = t * CPT_A + u;
        g_cs[b * (CELLS + 1) + c] = run;
        cnt[c] = run;
        run += loc[u];
    }
    if (t == 0) g_cs[b * (CELLS + 1) + CELLS] = NPTS;
    __syncthreads();

    #pragma unroll
    for (int s = 0; s < PPT_A; s++) {
        int k = t + s * TPB_A;
        int slot = atomicAdd(&cnt[cellof[s]], 1);
        g_pts[b * NPTS + slot] =
            make_float4(px[s], py[s], pz[s], __int_as_float(k));
    }
}

// ---------------- Kernel B: 8-lanes-per-query grid NN + epilogue -----------
typedef unsigned long long u64;
#define TPB_B 256
#define GSIZE 8
#define QPB (TPB_B / GSIZE)       // 32 queries per block

__global__ void __launch_bounds__(TPB_B) emd_query_kernel(
    const float* __restrict__ x1, float* __restrict__ out,
    const float* __restrict__ eps_p, const int* __restrict__ iters_p,
    int write_assign) {
    int sub  = threadIdx.x & (GSIZE - 1);             // lane within group
    int grp  = threadIdx.x >> 3;                      // group within block
    int gid  = blockIdx.x * QPB + grp;                // query id
    int b    = gid >> 11;                             // / NPTS

    const float* pq = x1 + (long)gid * 3;
    float x = pq[0], y = pq[1], z = pq[2];
    float sq1 = __fadd_rn(__fadd_rn(__fmul_rn(x, x), __fmul_rn(y, y)),
                          __fmul_rn(z, z));
    int cx = cell_coord(x), cy = cell_coord(y), cz = cell_coord(z);

    const float4* pts = g_pts + b * NPTS;
    const int*    cs  = g_cs + b * (CELLS + 1);

    u64 best = 0xFFFFFFFFFFFFFFFFull;

    // Scan one (zc,yc) row's x-contiguous candidate run, fold into best.
    auto scan_row = [&](int zc, int yc, int xlo, int xhi) {
        if ((unsigned)zc >= G || (unsigned)yc >= G) return;
        int row = (zc * G + yc) * G;
        int s = cs[row + xlo];
        int e = cs[row + xhi + 1];
        for (int k = s; k < e; k++) {
            float4 p = pts[k];
            float w = __fadd_rn(
                __fadd_rn(__fmul_rn(p.x, p.x), __fmul_rn(p.y, p.y)),
                __fmul_rn(p.z, p.z));
            float inner = __fmaf_rn(z, p.z,
                          __fmaf_rn(y, p.y, __fmul_rn(x, p.x)));
            float d2 = __fmaf_rn(-2.0f, inner, __fadd_rn(sq1, w));
            u64 key = ((u64)__float_as_uint(d2) << 32) |
                      (unsigned)__float_as_int(p.w);
            if (key < best) best = key;
        }
    };
    // Group butterfly u64-min (stays inside the 8-lane group).
    auto group_min = [&]() {
        #pragma unroll
        for (int off = GSIZE / 2; off > 0; off >>= 1) {
            u64 o = __shfl_xor_sync(0xFFFFFFFFu, best, off);
            if (o < best) best = o;
        }
    };

    // ---- r = 1 fast path: 9 rows, constant-divisor lane mapping ----
    {
        int xlo = cx - 1 < 0 ? 0 : cx - 1;
        int xhi = cx + 1 > G - 1 ? G - 1 : cx + 1;
        #pragma unroll
        for (int t = 0; t < 2; t++) {                 // t: sub, sub+8
            int rowid = sub + t * GSIZE;
            if (rowid < 9) {
                int dz = rowid / 3 - 1;               // constant div
                int dy = rowid - (rowid / 3) * 3 - 1;
                scan_row(cz + dz, cy + dy, xlo, xhi);
            }
        }
        group_min();
    }

    float bd2 = __uint_as_float((unsigned)(best >> 32));
    bool done = (bd2 < HCELL * HCELL - 1e-5f);

    // ---- general fallback: r = 2..G (rare, ~12% of queries) ----
    if (!done) {
        for (int r = 2; r <= G; r++) {
            int ny = 2 * r + 1;
            int nrow = ny * ny;
            int xlo = cx - r < 0 ? 0 : cx - r;
            int xhi = cx + r > G - 1 ? G - 1 : cx + r;
            for (int t = sub; t < nrow; t += GSIZE) {
                int q = t / ny;                        // runtime div, cold path
                scan_row(cz - r + q, cy - r + (t - q * ny), xlo, xhi);
            }
            group_min();
            float rh = (float)r * HCELL;
            bd2 = __uint_as_float((unsigned)(best >> 32));
            if (bd2 < rh * rh - 1e-5f) break;          // provably complete
        }                                              // r==G covers the grid
    }

    if (sub == 0) {
        float d2 = __uint_as_float((unsigned)(best >> 32));
        int   aj = (int)(best & 0xFFFFFFFFu);

        float cmin = sqrtf(fmaxf(d2, 0.0f));           // IEEE sqrt
        float eps  = eps_p   ? *eps_p   : 0.005f;
        int   iters = iters_p ? *iters_p : 50;

        float price = 0.0f;
        float m = 0.0f;
        if (iters == 50) {
            #pragma unroll
            for (int t = 0; t < 50; t++) {
                m = __fadd_rn(cmin, -price);
                price = __fadd_rn(price, __fmul_rn(eps, m));
            }
        } else {
            for (int t = 0; t < iters; t++) {
                m = __fadd_rn(cmin, -price);
                price = __fadd_rn(price, __fmul_rn(eps, m));
            }
        }

        out[gid] = sqrtf(m);
        if (write_assign) out[ROWS + gid] = (float)aj;
    }
}

extern "C" void kernel_launch(void* const* d_in, const int* in_sizes, int n_in,
                              void* d_out, int out_size) {
    const float* x1 = (const float*)d_in[0];
    const float* x2 = (const float*)d_in[1];
    const float* eps_p   = (n_in > 2) ? (const float*)d_in[2] : nullptr;
    const int*   iters_p = (n_in > 3) ? (const int*)d_in[3]   : nullptr;

    emd_bin_kernel<<<BATCH, TPB_A>>>(x2);

    int write_assign = (out_size >= 2 * ROWS) ? 1 : 0;
    emd_query_kernel<<<ROWS / QPB, TPB_B>>>(x1, (float*)d_out,
                                            eps_p, iters_p, write_assign);
}

// round 12
// speedup vs baseline: 1.6044x; 1.1745x over previous
#include <cuda_runtime.h>
#include <cuda_bf16.h>

// emdModule: exact NN via uniform-grid spatial hashing + 50-step recurrence.
// 8 lanes per query fast path (r=1 cube); warp-cooperative slow path for the
// ~12% of queries that need r>=2 (whole warp scans one pending query).
//
// EXACTNESS (outputs bit-identical to the passing brute-force kernels):
//  - d2 per examined candidate uses the identical rounded op sequence:
//      w     = (a*a + b*b) + c*c          (mul/add, no fma; precomputed at bin)
//      inner = fma(z,c, fma(y,b, x*a))
//      d2    = fma(-2, inner, sq1 + w)
//  - selection = min over packed key (bits(d2)<<32 | j): order- and
//    duplication-independent; ties -> smaller j == jnp.argmin first-index.
//    (This also makes the nondeterministic scatter order irrelevant.)
//  - completeness: after scanning the Chebyshev<=r cell cube, any unexamined
//    point differs by >= r+1 cells on some axis => exact dist >= r*h, so
//    rounded d2 >= (r*h)^2 - ~2e-6. Stop only when best_d2 < (r*h)^2 - 1e-5;
//    r == G covers the whole grid as fallback.
//  - epilogue identical: cmin = sqrt(max(d2,0)); iters x {m = cmin - price;
//    price += eps*m}; outputs sqrt(m), assignment.

#define BATCH 16
#define NPTS 2048
#define ROWS (BATCH * NPTS)   // 32768
#define G 16                  // grid resolution per axis
#define CELLS (G * G * G)     // 4096
#define HCELL 0.0625f         // 1/G, exactly representable

__device__ float4 g_pts[BATCH * NPTS];          // {a,b,c,w} cell-sorted
__device__ int    g_idx[BATCH * NPTS];          // original j per slot
__device__ int    g_cs[BATCH * (CELLS + 1)];    // exclusive starts + sentinel

__device__ __forceinline__ int cell_coord(float v) {
    int c = (int)(v * (float)G);
    return c < 0 ? 0 : (c > G - 1 ? G - 1 : c);
}

// ---------------- Kernel A: per-batch counting sort into cells -------------
#define TPB_A 512
#define PPT_A (NPTS / TPB_A)      // 4 points per thread
#define CPT_A (CELLS / TPB_A)     // 8 cells per thread

__global__ void __launch_bounds__(TPB_A) emd_bin_kernel(
    const float* __restrict__ x2) {
    int b = blockIdx.x;
    int t = threadIdx.x;
    __shared__ int cnt[CELLS];
    __shared__ int wsum[16];

    for (int c = t; c < CELLS; c += TPB_A) cnt[c] = 0;
    __syncthreads();

    int   cellof[PPT_A];
    float px[PPT_A], py[PPT_A], pz[PPT_A];
    #pragma unroll
    for (int s = 0; s < PPT_A; s++) {
        int k = t + s * TPB_A;
        const float* p = x2 + ((long)b * NPTS + k) * 3;
        float a = p[0], bb = p[1], cc = p[2];
        int c = (cell_coord(cc) * G + cell_coord(bb)) * G + cell_coord(a);
        px[s] = a; py[s] = bb; pz[s] = cc; cellof[s] = c;
        atomicAdd(&cnt[c], 1);
    }
    __syncthreads();

    int loc[CPT_A], tsum = 0;
    #pragma unroll
    for (int u = 0; u < CPT_A; u++) { loc[u] = cnt[t * CPT_A + u]; tsum += loc[u]; }
    int lane = t & 31, wid = t >> 5;
    int incl = tsum;
    #pragma unroll
    for (int off = 1; off < 32; off <<= 1) {
        int v = __shfl_up_sync(0xFFFFFFFFu, incl, off);
        if (lane >= off) incl += v;
    }
    if (lane == 31) wsum[wid] = incl;
    __syncthreads();
    if (t == 0) {
        int acc = 0;
        #pragma unroll
        for (int w = 0; w < 16; w++) { int v = wsum[w]; wsum[w] = acc; acc += v; }
    }
    __syncthreads();
    int run = wsum[wid] + (incl - tsum);
    __syncthreads();
    #pragma unroll
    for (int u = 0; u < CPT_A; u++) {
        int c = t * CPT_A + u;
        g_cs[b * (CELLS + 1) + c] = run;
        cnt[c] = run;
        run += loc[u];
    }
    if (t == 0) g_cs[b * (CELLS + 1) + CELLS] = NPTS;
    __syncthreads();

    #pragma unroll
    for (int s = 0; s < PPT_A; s++) {
        int k = t + s * TPB_A;
        float a = px[s], bb = py[s], cc = pz[s];
        // w with the exact reference op sequence: (a*a + b*b) + c*c
        float w = __fadd_rn(__fadd_rn(__fmul_rn(a, a), __fmul_rn(bb, bb)),
                            __fmul_rn(cc, cc));
        int slot = atomicAdd(&cnt[cellof[s]], 1);
        g_pts[b * NPTS + slot] = make_float4(a, bb, cc, w);
        g_idx[b * NPTS + slot] = k;
    }
}

// ---------------- Kernel B: grid NN query + epilogue -----------------------
typedef unsigned long long u64;
#define TPB_B 256
#define GSIZE 8
#define QPB (TPB_B / GSIZE)       // 32 queries per block (one batch per block)

__global__ void __launch_bounds__(TPB_B) emd_query_kernel(
    const float* __restrict__ x1, float* __restrict__ out,
    const float* __restrict__ eps_p, const int* __restrict__ iters_p,
    int write_assign) {
    int lane = threadIdx.x & 31;                      // lane in warp
    int sub  = lane & (GSIZE - 1);                    // lane in 8-group
    int grp  = threadIdx.x >> 3;                      // group in block
    int gid  = blockIdx.x * QPB + grp;                // query id
    int b    = gid >> 11;                             // batch (same for block)

    const float* pq = x1 + (long)gid * 3;
    float x = pq[0], y = pq[1], z = pq[2];
    float sq1 = __fadd_rn(__fadd_rn(__fmul_rn(x, x), __fmul_rn(y, y)),
                          __fmul_rn(z, z));
    int cx = cell_coord(x), cy = cell_coord(y), cz = cell_coord(z);

    const float4* __restrict__ pts = g_pts + b * NPTS;
    const int*    __restrict__ idx = g_idx + b * NPTS;
    const int*    __restrict__ cs  = g_cs + b * (CELLS + 1);

    // Scan one (zc,yc) row's x-contiguous candidate run; fold into acc.
    auto scan_row = [&](float qx, float qy, float qz, float qs,
                        int zc, int yc, int xlo, int xhi, u64& acc) {
        if ((unsigned)zc >= G || (unsigned)yc >= G) return;
        int row = (zc * G + yc) * G;
        int s = cs[row + xlo];
        int e = cs[row + xhi + 1];
        for (int k = s; k < e; k++) {
            float4 p = pts[k];
            float inner = __fmaf_rn(qz, p.z,
                          __fmaf_rn(qy, p.y, __fmul_rn(qx, p.x)));
            float d2 = __fmaf_rn(-2.0f, inner, __fadd_rn(qs, p.w));
            u64 key = ((u64)__float_as_uint(d2) << 32) | (unsigned)idx[k];
            if (key < acc) acc = key;
        }
    };

    u64 best = 0xFFFFFFFFFFFFFFFFull;

    // ---- fast path: r=1 cube, 9 rows over 8 lanes (2 rounds) ----
    {
        int xlo = cx - 1 < 0 ? 0 : cx - 1;
        int xhi = cx + 1 > G - 1 ? G - 1 : cx + 1;
        #pragma unroll
        for (int t = 0; t < 2; t++) {
            int rowid = sub + t * GSIZE;
            if (rowid < 9) {
                int dz = rowid / 3 - 1;               // constant div -> mul
                int dy = rowid - (rowid / 3) * 3 - 1;
                scan_row(x, y, z, sq1, cz + dz, cy + dy, xlo, xhi, best);
            }
        }
        #pragma unroll
        for (int off = GSIZE / 2; off > 0; off >>= 1) {
            u64 o = __shfl_xor_sync(0xFFFFFFFFu, best, off);
            if (o < best) best = o;
        }
    }
    float bd2 = __uint_as_float((unsigned)(best >> 32));
    bool done = (bd2 < HCELL * HCELL - 1e-5f);

    // ---- warp-cooperative slow path: each pending query gets all 32 lanes --
    unsigned pending = __ballot_sync(0xFFFFFFFFu, sub == 0 && !done);
    while (pending) {
        int src = __ffs(pending) - 1;                 // lane owning the query
        pending &= pending - 1;
        float qx = __shfl_sync(0xFFFFFFFFu, x,   src);
        float qy = __shfl_sync(0xFFFFFFFFu, y,   src);
        float qz = __shfl_sync(0xFFFFFFFFu, z,   src);
        float qs = __shfl_sync(0xFFFFFFFFu, sq1, src);
        int  qcx = __shfl_sync(0xFFFFFFFFu, cx,  src);
        int  qcy = __shfl_sync(0xFFFFFFFFu, cy,  src);
        int  qcz = __shfl_sync(0xFFFFFFFFu, cz,  src);
        u64 wb   = __shfl_sync(0xFFFFFFFFu, best, src);

        // r=2: 25 rows over 32 lanes, one round, ny=5 compile-time
        {
            int xlo = qcx - 2 < 0 ? 0 : qcx - 2;
            int xhi = qcx + 2 > G - 1 ? G - 1 : qcx + 2;
            if (lane < 25) {
                int dz = lane / 5 - 2;
                int dy = lane - (lane / 5) * 5 - 2;
                scan_row(qx, qy, qz, qs, qcz + dz, qcy + dy, xlo, xhi, wb);
            }
            #pragma unroll
            for (int off = 16; off > 0; off >>= 1) {
                u64 o = __shfl_xor_sync(0xFFFFFFFFu, wb, off);
                if (o < wb) wb = o;
            }
        }
        float wd2 = __uint_as_float((unsigned)(wb >> 32));
        if (!(wd2 < 4.0f * HCELL * HCELL - 1e-5f)) {
            // r>=3: astronomically rare; kept for exactness. r==G covers grid.
            for (int r = 3; r <= G; r++) {
                int ny = 2 * r + 1, nrow = ny * ny;
                int xlo = qcx - r < 0 ? 0 : qcx - r;
                int xhi = qcx + r > G - 1 ? G - 1 : qcx + r;
                for (int t = lane; t < nrow; t += 32) {
                    int qd = t / ny;
                    scan_row(qx, qy, qz, qs, qcz - r + qd,
                             qcy - r + (t - qd * ny), xlo, xhi, wb);
                }
                #pragma unroll
                for (int off = 16; off > 0; off >>= 1) {
                    u64 o = __shfl_xor_sync(0xFFFFFFFFu, wb, off);
                    if (o < wb) wb = o;
                }
                wd2 = __uint_as_float((unsigned)(wb >> 32));
                float rh = (float)r * HCELL;
                if (wd2 < rh * rh - 1e-5f) break;
            }
        }
        if (lane == src) best = wb;                   // return to owner lane
    }

    // ---- epilogue: one active lane per query (4 per warp, amortized) ----
    if (sub == 0) {
        float d2 = __uint_as_float((unsigned)(best >> 32));
        int   aj = (int)(best & 0xFFFFFFFFu);

        float cmin = sqrtf(fmaxf(d2, 0.0f));          // IEEE sqrt
        float eps  = eps_p   ? *eps_p   : 0.005f;
        int   iters = iters_p ? *iters_p : 50;

        float price = 0.0f;
        float m = 0.0f;
        if (iters == 50) {
            #pragma unroll
            for (int t = 0; t < 50; t++) {
                m = __fadd_rn(cmin, -price);
                price = __fadd_rn(price, __fmul_rn(eps, m));
            }
        } else {
            for (int t = 0; t < iters; t++) {
                m = __fadd_rn(cmin, -price);
                price = __fadd_rn(price, __fmul_rn(eps, m));
            }
        }

        out[gid] = sqrtf(m);
        if (write_assign) out[ROWS + gid] = (float)aj;
    }
}

extern "C" void kernel_launch(void* const* d_in, const int* in_sizes, int n_in,
                              void* d_out, int out_size) {
    const float* x1 = (const float*)d_in[0];
    const float* x2 = (const float*)d_in[1];
    const float* eps_p   = (n_in > 2) ? (const float*)d_in[2] : nullptr;
    const int*   iters_p = (n_in > 3) ? (const int*)d_in[3]   : nullptr;

    emd_bin_kernel<<<BATCH, TPB_A>>>(x2);

    int write_assign = (out_size >= 2 * ROWS) ? 1 : 0;
    emd_query_kernel<<<ROWS / QPB, TPB_B>>>(x1, (float*)d_out,
                                            eps_p, iters_p, write_assign);
}